// round 15
// baseline (speedup 1.0000x reference)
#include <cuda_runtime.h>
#include <cuda_bf16.h>
#include <math.h>
#include <stdint.h>

#define TOKENS 32768
#define LSEQ   512
#define HID    128
#define VD     256
#define FFND   256
#define QKN    768   // 128 Q | 128 K | 256 V | 256 G

typedef unsigned short u16;

// fp32 row-major buffers
__device__ float g_X [TOKENS * HID];
__device__ float g_Y1[TOKENS * HID];
// bf16 buffers
__device__ u16 g_G [TOKENS * VD];
__device__ u16 g_Xn[TOKENS * HID];
__device__ u16 g_P [TOKENS * VD];
__device__ u16 g_Hf[TOKENS * FFND];
__device__ u16 g_Qf[64*4*16384];
__device__ u16 g_Kf[64*4*16384];
__device__ u16 g_Vf[(size_t)64*4*32768];
__device__ u16 g_Wq[4 * HID * QKN];
__device__ u16 g_Wo[4 * VD * HID];
__device__ u16 g_W1[4 * HID * FFND];
__device__ u16 g_W2[4 * FFND * HID];
__device__ float g_qc[LSEQ*16], g_qs[LSEQ*16], g_kc[LSEQ*16], g_ks[LSEQ*16];
__device__ float g_lg2g[4];

__device__ __forceinline__ float geluf(float v){ return 0.5f*v*(1.0f+erff(v*0.70710678f)); }
__device__ __forceinline__ float siluf(float v){ return v/(1.0f+expf(-v)); }
__device__ __forceinline__ unsigned bf2(float a, float b){
    __nv_bfloat162 t = __floats2bfloat162_rn(a, b);
    return *(unsigned*)&t;
}
__device__ __forceinline__ u16 bf1(float a){
    __nv_bfloat16 t = __float2bfloat16_rn(a);
    return *(u16*)&t;
}
__device__ __forceinline__ float2 unbf2(unsigned u){
    __nv_bfloat162 t = *(__nv_bfloat162*)&u;
    return __bfloat1622float2(t);
}
__device__ __forceinline__ void mma_bf16(float* d, const unsigned* a, const unsigned* b){
    asm volatile("mma.sync.aligned.m16n8k16.row.col.f32.bf16.bf16.f32 "
        "{%0,%1,%2,%3},{%4,%5,%6,%7},{%8,%9},{%0,%1,%2,%3};"
        : "+f"(d[0]),"+f"(d[1]),"+f"(d[2]),"+f"(d[3])
        : "r"(a[0]),"r"(a[1]),"r"(a[2]),"r"(a[3]), "r"(b[0]),"r"(b[1]));
}
__device__ __forceinline__ void cpa16(u16* dst, const u16* src){
    unsigned d = (unsigned)__cvta_generic_to_shared(dst);
    asm volatile("cp.async.cg.shared.global [%0], [%1], 16;" :: "r"(d), "l"(src));
}

// A-fragment ushort index, m16n8k16 bf16. Kt = K/16.
__device__ __forceinline__ size_t a16(int row, int k, int Kt){
    return ((size_t)((row>>4)*Kt + (k>>4)))*256 +
           (size_t)(((row&7)*4 + ((k&7)>>1))*8 + (((row>>3)&1) + (((k>>3)&1)<<1))*2 + (k&1));
}
// B-fragment ushort index
__device__ __forceinline__ size_t b16(int k, int n, int Kt){
    return ((size_t)((n>>3)*Kt + (k>>4)))*128 +
           (size_t)(((n&7)*4 + ((k&7)>>1))*4 + (((k>>3)&1)<<1) + (k&1));
}

// ------------------- xpos tables + per-head log2(gamma) -------------------
__global__ void xpos_table_kernel(){
    int idx = blockIdx.x*256 + threadIdx.x;
    if (idx < 4){
        double lgA=-3.4657359027997265, lgB=-6.2383246250395075;
        g_lg2g[idx] = (float)(log(1.0 - exp(lgA + (lgB-lgA)*(double)idx/3.0)) * 1.4426950408889634);
    }
    if (idx >= LSEQ*16) return;
    int l = idx >> 4, j = idx & 15;
    float base = ((float)j + 12.8f) / 44.8f;
    float sc   = powf(base, (float)l / 512.0f);
    float ang  = (float)l * powf(10000.0f, -(float)j/16.0f);
    float s, c; sincosf(ang, &s, &c);
    g_qc[idx]=c*sc; g_qs[idx]=s*sc; g_kc[idx]=c/sc; g_ks[idx]=s/sc;
}

// ------------------- ALL weights -> bf16 B-fragment layout -------------------
__global__ void wfrag_all_kernel(
    const float* __restrict__ wq, const float* __restrict__ wk,
    const float* __restrict__ wv, const float* __restrict__ wg,
    const float* __restrict__ wo, const float* __restrict__ w1,
    const float* __restrict__ w2)
{
    int idx = blockIdx.x*256 + threadIdx.x;
    int l = idx / 196608, r = idx % 196608;
    if (r < 98304){
        int k = r / QKN, n = r % QKN;
        float v;
        if (n < 128)      v = wq[(((size_t)l*4 + (n>>5))*HID + k)*32 + (n&31)];
        else if (n < 256) { int c=n-128; v = wk[(((size_t)l*4 + (c>>5))*HID + k)*32 + (c&31)]; }
        else if (n < 512) { int c=n-256; v = wv[(((size_t)l*4 + (c>>6))*HID + k)*64 + (c&63)]; }
        else              v = wg[((size_t)l*HID + k)*VD + (n-512)];
        g_Wq[(size_t)l*HID*QKN + b16(k, n, 8)] = bf1(v);
    } else {
        int r2 = r - 98304;
        int m = r2 >> 15, e = r2 & 32767;
        if (m == 0){
            int k = e >> 7, n = e & 127;
            g_Wo[(size_t)l*VD*HID + b16(k, n, 16)] =
                bf1(wo[(size_t)l*VD*HID + (size_t)k*HID + n]);
        } else if (m == 1){
            int k = e >> 8, n = e & 255;
            g_W1[(size_t)l*HID*FFND + b16(k, n, 8)] =
                bf1(w1[(size_t)l*HID*FFND + (size_t)k*FFND + n]);
        } else {
            int k = e >> 7, n = e & 127;
            g_W2[(size_t)l*FFND*HID + b16(k, n, 16)] =
                bf1(w2[(size_t)l*FFND*HID + (size_t)k*HID + n]);
        }
    }
}

// ------------------- input MLP -------------------
__global__ __launch_bounds__(256) void rem_kernel(
    const float* __restrict__ x,
    const float* __restrict__ w1, const float* __restrict__ b1,
    const float* __restrict__ w2, const float* __restrict__ b2,
    const float* __restrict__ w3, const float* __restrict__ b3,
    float* __restrict__ X)
{
    __shared__ float sw1[160], sb1[32], sw2[2048], sb2[64], sw3[8192], sb3[128];
    int tid = threadIdx.x;
    for (int i=tid;i<160; i+=256) sw1[i]=w1[i];
    for (int i=tid;i<2048;i+=256) sw2[i]=w2[i];
    for (int i=tid;i<8192;i+=256) sw3[i]=w3[i];
    if (tid<32)  sb1[tid]=b1[tid];
    if (tid<64)  sb2[tid]=b2[tid];
    if (tid<128) sb3[tid]=b3[tid];
    __syncthreads();
    int t = blockIdx.x*256 + tid;
    float xin[5];
#pragma unroll
    for (int k=0;k<5;k++) xin[k] = x[(size_t)t*5+k];
    float h1[32];
#pragma unroll
    for (int o=0;o<32;o++){ float s=sb1[o];
#pragma unroll
        for (int k=0;k<5;k++) s += xin[k]*sw1[k*32+o];
        h1[o]=geluf(s); }
    float h2[64];
#pragma unroll
    for (int o=0;o<64;o++){ float s=sb2[o];
#pragma unroll
        for (int k=0;k<32;k++) s += h1[k]*sw2[k*64+o];
        h2[o]=geluf(s); }
    for (int o=0;o<128;o+=4){
        float v0=sb3[o],v1=sb3[o+1],v2=sb3[o+2],v3=sb3[o+3];
#pragma unroll
        for (int k=0;k<64;k++){ float hk=h2[k];
            v0+=hk*sw3[k*128+o]; v1+=hk*sw3[k*128+o+1];
            v2+=hk*sw3[k*128+o+2]; v3+=hk*sw3[k*128+o+3]; }
        *(float4*)(X+(size_t)t*128+o) = make_float4(geluf(v0),geluf(v1),geluf(v2),geluf(v3));
    }
}

// ------------------- LayerNorm(128) -> bf16 A-fragment layout -------------------
__global__ __launch_bounds__(256) void ln_frag_kernel(
    const float* __restrict__ X, const float* __restrict__ w,
    const float* __restrict__ b, u16* __restrict__ out)
{
    int g = blockIdx.x*256 + threadIdx.x;
    int row = g>>5, lane = g&31;
    float4 v = *(const float4*)(X + (size_t)row*128 + lane*4);
    float s = v.x+v.y+v.z+v.w;
    float s2 = v.x*v.x+v.y*v.y+v.z*v.z+v.w*v.w;
#pragma unroll
    for (int o=16;o;o>>=1){ s += __shfl_xor_sync(~0u,s,o); s2 += __shfl_xor_sync(~0u,s2,o); }
    float mean = s*(1.f/128.f), var = s2*(1.f/128.f)-mean*mean;
    float rstd = rsqrtf(var + 1e-5f);
    float4 wv = *(const float4*)(w+lane*4), bv = *(const float4*)(b+lane*4);
    float rv[4];
    rv[0]=(v.x-mean)*rstd*wv.x+bv.x; rv[1]=(v.y-mean)*rstd*wv.y+bv.y;
    rv[2]=(v.z-mean)*rstd*wv.z+bv.z; rv[3]=(v.w-mean)*rstd*wv.w+bv.w;
    int k0 = lane*4;
    *(unsigned*)(out + a16(row, k0,   8)) = bf2(rv[0], rv[1]);
    *(unsigned*)(out + a16(row, k0+2, 8)) = bf2(rv[2], rv[3]);
}

// ------------------- bf16 frag-fed GEMM, 256x64 block. OP: 1 gelu->Afrag, 3 residual ----
template<int OP>
__global__ __launch_bounds__(256) void gemm_f(
    const u16* __restrict__ Af, const u16* __restrict__ Bf,
    const float* __restrict__ bias, const float* __restrict__ R,
    float* __restrict__ Cf, u16* __restrict__ Ca, int N, int K)
{
    const int tid = threadIdx.x, lane = tid & 31, wid = tid >> 5;
    const int wm = wid & 3, wn = wid >> 2;
    const int m0 = blockIdx.y*256, n0 = blockIdx.x*64;
    const int Kt = K >> 4;

    float acc[4][4][4];
#pragma unroll
    for (int i=0;i<4;i++)
#pragma unroll
        for (int j=0;j<4;j++)
#pragma unroll
            for (int u=0;u<4;u++) acc[i][j][u]=0.f;

    const u16* Ab = Af + ((size_t)((m0>>4) + wm*4))*Kt*256 + lane*8;
    const u16* Bb = Bf + ((size_t)((n0>>3) + wn*4))*Kt*128 + lane*4;

#pragma unroll 2
    for (int kc = 0; kc < Kt; kc++){
        unsigned a[4][4], b[4][2];
#pragma unroll
        for (int mi=0;mi<4;mi++){
            uint4 t = *(const uint4*)(Ab + ((size_t)(mi*Kt + kc))*256);
            a[mi][0]=t.x; a[mi][1]=t.y; a[mi][2]=t.z; a[mi][3]=t.w;
        }
#pragma unroll
        for (int ni=0;ni<4;ni++){
            uint2 t = *(const uint2*)(Bb + ((size_t)(ni*Kt + kc))*128);
            b[ni][0]=t.x; b[ni][1]=t.y;
        }
#pragma unroll
        for (int mi=0;mi<4;mi++)
#pragma unroll
            for (int ni=0;ni<4;ni++)
                mma_bf16(acc[mi][ni], a[mi], b[ni]);
    }

    const int gid = lane>>2, tig = lane&3;
#pragma unroll
    for (int mi=0;mi<4;mi++)
#pragma unroll
        for (int ni=0;ni<4;ni++){
            int col = n0 + wn*32 + ni*8 + tig*2;
            float bb0=0.f, bb1=0.f;
            if (bias){ float2 bv = *(const float2*)(bias+col); bb0=bv.x; bb1=bv.y; }
#pragma unroll
            for (int hh=0; hh<2; hh++){
                int row = m0 + wm*64 + mi*16 + gid + hh*8;
                float v0 = acc[mi][ni][hh*2+0] + bb0;
                float v1 = acc[mi][ni][hh*2+1] + bb1;
                if (OP==1){
                    v0 = geluf(v0); v1 = geluf(v1);
                    *(unsigned*)(Ca + a16(row, col, N>>4)) = bf2(v0, v1);
                } else {
                    float2 rv = *(const float2*)(R + (size_t)row*N + col);
                    v0+=rv.x; v1+=rv.y;
                    *(float2*)(Cf + (size_t)row*N + col) = make_float2(v0,v1);
                }
            }
        }
}

// ------------------- QKVG GEMM: 256x64 block, epilogue -> per-head bf16 frag buffers ----
// exp2f hoisted: one scale per output row per thread (8 total), reused across ni.
__global__ __launch_bounds__(256) void gemm_qkvg(
    const u16* __restrict__ Af, const u16* __restrict__ Bf)
{
    const int tid = threadIdx.x, lane = tid & 31, wid = tid >> 5;
    const int wm = wid & 3, wn = wid >> 2;
    const int m0 = blockIdx.y*256, n0 = blockIdx.x*64;
    const int Kt = 8;

    float acc[4][4][4];
#pragma unroll
    for (int i=0;i<4;i++)
#pragma unroll
        for (int j=0;j<4;j++)
#pragma unroll
            for (int u=0;u<4;u++) acc[i][j][u]=0.f;

    const u16* Ab = Af + ((size_t)((m0>>4) + wm*4))*Kt*256 + lane*8;
    const u16* Bb = Bf + ((size_t)((n0>>3) + wn*4))*Kt*128 + lane*4;

#pragma unroll 2
    for (int kc = 0; kc < Kt; kc++){
        unsigned a[4][4], b[4][2];
#pragma unroll
        for (int mi=0;mi<4;mi++){
            uint4 t = *(const uint4*)(Ab + ((size_t)(mi*Kt + kc))*256);
            a[mi][0]=t.x; a[mi][1]=t.y; a[mi][2]=t.z; a[mi][3]=t.w;
        }
#pragma unroll
        for (int ni=0;ni<4;ni++){
            uint2 t = *(const uint2*)(Bb + ((size_t)(ni*Kt + kc))*128);
            b[ni][0]=t.x; b[ni][1]=t.y;
        }
#pragma unroll
        for (int mi=0;mi<4;mi++)
#pragma unroll
            for (int ni=0;ni<4;ni++)
                mma_bf16(acc[mi][ni], a[mi], b[ni]);
    }

    const int gid = lane>>2, tig = lane&3;
    const int cbase = n0 + wn*32;          // warp's 32-col span: one region, one head
    // hoisted per-row decay scales for Q/K regions
    float scr[4][2];
    if (cbase < 256){
        const bool isQ = (cbase < 128);
        const int h = (isQ ? cbase : cbase-128) >> 5;
        const float lg = isQ ? g_lg2g[h] : -g_lg2g[h];
#pragma unroll
        for (int mi=0;mi<4;mi++)
#pragma unroll
            for (int hh=0;hh<2;hh++){
                int ii = (m0 + wm*64 + mi*16 + gid + hh*8) & 511;
                scr[mi][hh] = exp2f((float)ii * lg);
            }
    }

#pragma unroll
    for (int mi=0;mi<4;mi++)
#pragma unroll
        for (int ni=0;ni<4;ni++){
            int col = cbase + ni*8 + tig*2;
#pragma unroll
            for (int hh=0; hh<2; hh++){
                int t = m0 + wm*64 + mi*16 + gid + hh*8;
                int bb = t >> 9, ii = t & 511;
                float v0 = acc[mi][ni][hh*2+0];
                float v1 = acc[mi][ni][hh*2+1];
                if (col < 256){
                    const float* ct = (col<128)? g_qc : g_kc;
                    const float* st = (col<128)? g_qs : g_ks;
                    int j = (col&31)>>1;
                    float c0=ct[ii*16+j], s0=st[ii*16+j];
                    float t0 = v0*c0 - v1*s0, t1 = v1*c0 + v0*s0;
                    float sc = scr[mi][hh];
                    if (col < 128){
                        int h = col>>5, d = col&31;
                        u16* dst = g_Qf + ((size_t)(bb*4+h))*16384;
                        *(unsigned*)(dst + a16(ii, d, 2)) = bf2(t0*sc, t1*sc);
                    } else {
                        int h = (col-128)>>5, d = (col-128)&31;
                        u16* dst = g_Kf + ((size_t)(bb*4+h))*16384;
                        *(unsigned*)(dst + b16(d, ii, 2)) = bf2(t0*sc, t1*sc);
                    }
                } else if (col < 512){
                    int h = (col-256)>>6, v = (col-256)&63;
                    u16* dst = g_Vf + ((size_t)(bb*4+h))*32768;
                    dst[b16(ii, v,   32)] = bf1(v0);
                    dst[b16(ii, v+1, 32)] = bf1(v1);
                } else {
                    *(unsigned*)(g_G + (size_t)t*VD + (col-512)) = bf2(v0, v1);
                }
            }
        }
}

// ------------------- Retention: S in registers, cp.async double-buffered K/V -------------------
#define RET_SMEM 24576
__global__ __launch_bounds__(256) void retention_kernel(
    const u16* __restrict__ Qf, const u16* __restrict__ Kf,
    const u16* __restrict__ Vf, const u16* __restrict__ G,
    const float* __restrict__ gn_w, const float* __restrict__ gn_b,
    u16* __restrict__ P)
{
    extern __shared__ u16 smu[];
    u16* KsB = smu;          // 2 x 2048
    u16* VsB = smu + 4096;   // 2 x 4096

    const int tid = threadIdx.x, lane = tid&31, wm = tid>>5;
    const int gid = lane>>2, tig = lane&3;
    const int qt = blockIdx.x, h = blockIdx.y, b = blockIdx.z;
    const int l0 = qt*128;
    const size_t rb = (size_t)b*512;
    const size_t bh = (size_t)(b*4 + h);
    const u16* Qg = Qf + bh*16384;
    const u16* Kg = Kf + bh*16384;
    const u16* Vg = Vf + bh*32768;

    unsigned qf[2][4];
#pragma unroll
    for (int kc=0; kc<2; kc++){
        uint4 t = *(const uint4*)(Qg + ((size_t)(((l0>>4)+wm)*2 + kc))*256 + lane*8);
        qf[kc][0]=t.x; qf[kc][1]=t.y; qf[kc][2]=t.z; qf[kc][3]=t.w;
    }

    float yacc[8][4];
#pragma unroll
    for (int j=0;j<8;j++)
#pragma unroll
        for (int u=0;u<4;u++) yacc[j][u]=0.f;

    const int ntile = 2*qt + 2;
    const int vg0 = tid >> 6, vrem0 = tid & 63;
    const int vg1 = (tid+256) >> 6, vrem1 = (tid+256) & 63;

    {
        cpa16(KsB + tid*8, Kg + (size_t)0*2048 + tid*8);
        cpa16(VsB + (size_t)tid*8,        Vg + ((size_t)(vg0*32 + 0*4)*16 + vrem0)*8);
        cpa16(VsB + (size_t)(tid+256)*8,  Vg + ((size_t)(vg1*32 + 0*4)*16 + vrem1)*8);
        asm volatile("cp.async.commit_group;");
    }

    for (int mt=0; mt<ntile; mt++){
        const int cur = mt & 1;
        const int doff = mt*64 - l0;
        if (mt+1 < ntile){
            int nb = cur ^ 1;
            cpa16(KsB + nb*2048 + tid*8, Kg + (size_t)(mt+1)*2048 + tid*8);
            cpa16(VsB + nb*4096 + (size_t)tid*8,       Vg + ((size_t)(vg0*32 + (mt+1)*4)*16 + vrem0)*8);
            cpa16(VsB + nb*4096 + (size_t)(tid+256)*8, Vg + ((size_t)(vg1*32 + (mt+1)*4)*16 + vrem1)*8);
            asm volatile("cp.async.commit_group;");
            asm volatile("cp.async.wait_group 1;");
        } else {
            asm volatile("cp.async.wait_group 0;");
        }
        __syncthreads();

        const u16* Ks = KsB + cur*2048;
        const u16* Vs = VsB + cur*4096;

        float sacc[8][4];
#pragma unroll
        for (int j=0;j<8;j++)
#pragma unroll
            for (int u=0;u<4;u++) sacc[j][u]=0.f;
#pragma unroll
        for (int kc=0; kc<2; kc++){
#pragma unroll
            for (int nj=0;nj<8;nj++){
                uint2 bt = *(const uint2*)(Ks + (size_t)(nj*2+kc)*128 + lane*4);
                unsigned bfr[2] = {bt.x, bt.y};
                mma_bf16(sacc[nj], qf[kc], bfr);
            }
        }
        if (doff >= 0){
#pragma unroll
            for (int nj=0;nj<8;nj++){
                int jb = nj*8 + tig*2 + doff;
#pragma unroll
                for (int ih=0; ih<2; ih++){
                    int i = wm*16 + gid + ih*8;
                    if (i < jb)   sacc[nj][ih*2+0] = 0.f;
                    if (i < jb+1) sacc[nj][ih*2+1] = 0.f;
                }
            }
        }
#pragma unroll
        for (int kc=0; kc<4; kc++){
            unsigned a[4];
            a[0] = bf2(sacc[2*kc  ][0], sacc[2*kc  ][1]);
            a[1] = bf2(sacc[2*kc  ][2], sacc[2*kc  ][3]);
            a[2] = bf2(sacc[2*kc+1][0], sacc[2*kc+1][1]);
            a[3] = bf2(sacc[2*kc+1][2], sacc[2*kc+1][3]);
#pragma unroll
            for (int nj=0;nj<8;nj++){
                uint2 bt = *(const uint2*)(Vs + (size_t)(nj*4+kc)*128 + lane*4);
                unsigned bfr[2] = {bt.x, bt.y};
                mma_bf16(yacc[nj], a, bfr);
            }
        }
        __syncthreads();
    }

    float s[2]={0.f,0.f}, q[2]={0.f,0.f};
#pragma unroll
    for (int nj=0;nj<8;nj++){
#pragma unroll
        for (int ih=0; ih<2; ih++){
            float v0 = yacc[nj][ih*2+0], v1 = yacc[nj][ih*2+1];
            s[ih] += v0 + v1;
            q[ih] += v0*v0 + v1*v1;
        }
    }
#pragma unroll
    for (int o=1;o<4;o<<=1){
        s[0] += __shfl_xor_sync(~0u, s[0], o);
        q[0] += __shfl_xor_sync(~0u, q[0], o);
        s[1] += __shfl_xor_sync(~0u, s[1], o);
        q[1] += __shfl_xor_sync(~0u, q[1], o);
    }
    float mean[2], rstd[2];
#pragma unroll
    for (int ih=0; ih<2; ih++){
        mean[ih] = s[ih]*(1.f/64.f);
        float var = q[ih]*(1.f/64.f) - mean[ih]*mean[ih];
        rstd[ih] = rsqrtf(var + 1e-5f);
    }
#pragma unroll
    for (int nj=0;nj<8;nj++){
        int col = nj*8 + tig*2;
        int k = h*64 + col;
        float2 wv = *(const float2*)(gn_w + k);
        float2 bv = *(const float2*)(gn_b + k);
#pragma unroll
        for (int ih=0; ih<2; ih++){
            int rowt = (int)(rb + l0 + wm*16 + gid + ih*8);
            unsigned gp = *(const unsigned*)(G + (size_t)rowt*VD + k);
            float2 gg = unbf2(gp);
            float o0 = ((yacc[nj][ih*2+0]-mean[ih])*rstd[ih]*wv.x + bv.x)*siluf(gg.x);
            float o1 = ((yacc[nj][ih*2+1]-mean[ih])*rstd[ih]*wv.y + bv.y)*siluf(gg.y);
            *(unsigned*)(P + a16(rowt, k, 16)) = bf2(o0, o1);
        }
    }
}

// ------------------- decoder + softmax -------------------
__global__ __launch_bounds__(256) void dec_kernel(
    const float* __restrict__ X, const float* __restrict__ w1, const float* __restrict__ b1,
    const float* __restrict__ w2, const float* __restrict__ b2, float* __restrict__ out)
{
    __shared__ float sw1[8192], sw2[1280], sb1[64], sb2[20];
    int tid = threadIdx.x;
    for (int i=tid;i<8192;i+=256) sw1[i]=w1[i];
    for (int i=tid;i<1280;i+=256) sw2[i]=w2[i];
    if (tid<64) sb1[tid]=b1[tid];
    if (tid<20) sb2[tid]=b2[tid];
    __syncthreads();
    int t = blockIdx.x*256 + tid;
    float h[64];
#pragma unroll
    for (int o=0;o<64;o++) h[o]=sb1[o];
    for (int k=0;k<128;k+=4){
        float4 xv = *(const float4*)(X + (size_t)t*128 + k);
#pragma unroll
        for (int o=0;o<64;o++){
            h[o] += xv.x*sw1[(k+0)*64+o] + xv.y*sw1[(k+1)*64+o]
                  + xv.z*sw1[(k+2)*64+o] + xv.w*sw1[(k+3)*64+o];
        }
    }
#pragma unroll
    for (int o=0;o<64;o++) h[o]=geluf(h[o]);
    float lg[20];
#pragma unroll
    for (int o=0;o<20;o++){ float s=sb2[o];
#pragma unroll
        for (int k=0;k<64;k++) s += h[k]*sw2[k*20+o];
        lg[o]=s; }
    float mx = lg[0];
#pragma unroll
    for (int o=1;o<20;o++) mx = fmaxf(mx, lg[o]);
    float sum = 0.f;
#pragma unroll
    for (int o=0;o<20;o++){ lg[o] = expf(lg[o]-mx); sum += lg[o]; }
    float inv = 1.0f/sum;
#pragma unroll
    for (int o=0;o<20;o++) out[(size_t)t*20+o] = lg[o]*inv;
}

// ------------------- launch -------------------
extern "C" void kernel_launch(void* const* d_in, const int* in_sizes, int n_in,
                              void* d_out, int out_size)
{
    const float* x      = (const float*)d_in[0];
    const float* rem_w1 = (const float*)d_in[1];
    const float* rem_b1 = (const float*)d_in[2];
    const float* rem_w2 = (const float*)d_in[3];
    const float* rem_b2 = (const float*)d_in[4];
    const float* rem_w3 = (const float*)d_in[5];
    const float* rem_b3 = (const float*)d_in[6];
    const float* wq     = (const float*)d_in[7];
    const float* wk     = (const float*)d_in[8];
    const float* wv     = (const float*)d_in[9];
    const float* wg     = (const float*)d_in[10];
    const float* wo     = (const float*)d_in[11];
    const float* gn_w   = (const float*)d_in[12];
    const float* gn_b   = (const float*)d_in[13];
    const float* ln1_w  = (const float*)d_in[14];
    const float* ln1_b  = (const float*)d_in[15];
    const float* ln2_w  = (const float*)d_in[16];
    const float* ln2_b  = (const float*)d_in[17];
    const float* ffn_w1 = (const float*)d_in[18];
    const float* ffn_b1 = (const float*)d_in[19];
    const float* ffn_w2 = (const float*)d_in[20];
    const float* ffn_b2 = (const float*)d_in[21];
    const float* dec_w1 = (const float*)d_in[22];
    const float* dec_b1 = (const float*)d_in[23];
    const float* dec_w2 = (const float*)d_in[24];
    const float* dec_b2 = (const float*)d_in[25];
    float* out = (float*)d_out;

    float *pX,*pY1;
    u16 *pG,*pXn,*pP,*pHf,*pWq,*pWo,*pW1,*pW2,*pQf,*pKf,*pVf;
    cudaGetSymbolAddress((void**)&pX,  g_X);
    cudaGetSymbolAddress((void**)&pY1, g_Y1);
    cudaGetSymbolAddress((void**)&pG,  g_G);
    cudaGetSymbolAddress((void**)&pXn, g_Xn);
    cudaGetSymbolAddress((void**)&pP,  g_P);
    cudaGetSymbolAddress((void**)&pHf, g_Hf);
    cudaGetSymbolAddress((void**)&pWq, g_Wq);
    cudaGetSymbolAddress((void**)&pWo, g_Wo);
    cudaGetSymbolAddress((void**)&pW1, g_W1);
    cudaGetSymbolAddress((void**)&pW2, g_W2);
    cudaGetSymbolAddress((void**)&pQf, g_Qf);
    cudaGetSymbolAddress((void**)&pKf, g_Kf);
    cudaGetSymbolAddress((void**)&pVf, g_Vf);

    xpos_table_kernel<<<32, 256>>>();
    wfrag_all_kernel<<<(4*196608)/256, 256>>>(wq, wk, wv, wg, wo, ffn_w1, ffn_w2);
    rem_kernel<<<TOKENS/256, 256>>>(x, rem_w1, rem_b1, rem_w2, rem_b2, rem_w3, rem_b3, pX);

    for (int l = 0; l < 4; l++){
        ln_frag_kernel<<<TOKENS/8, 256>>>(pX, ln1_w + l*128, ln1_b + l*128, pXn);
        gemm_qkvg<<<dim3(QKN/64, TOKENS/256), 256>>>(pXn, pWq + (size_t)l*HID*QKN);
        retention_kernel<<<dim3(4, 4, 64), 256, RET_SMEM>>>(
            pQf, pKf, pVf, pG, gn_w + l*VD, gn_b + l*VD, pP);
        gemm_f<3><<<dim3(HID/64, TOKENS/256), 256>>>(
            pP, pWo + (size_t)l*VD*HID, nullptr, pX, pY1, nullptr, HID, VD);
        ln_frag_kernel<<<TOKENS/8, 256>>>(pY1, ln2_w + l*128, ln2_b + l*128, pXn);
        gemm_f<1><<<dim3(FFND/64, TOKENS/256), 256>>>(
            pXn, pW1 + (size_t)l*HID*FFND, ffn_b1 + l*FFND, nullptr, nullptr, pHf, FFND, HID);
        gemm_f<3><<<dim3(HID/64, TOKENS/256), 256>>>(
            pHf, pW2 + (size_t)l*FFND*HID, ffn_b2 + l*HID, pY1, pX, nullptr, HID, FFND);
    }
    dec_kernel<<<TOKENS/256, 256>>>(pX, dec_w1, dec_b1, dec_w2, dec_b2, out);
}

// round 16
// speedup vs baseline: 1.0910x; 1.0910x over previous
#include <cuda_runtime.h>
#include <cuda_bf16.h>
#include <math.h>
#include <stdint.h>

#define TOKENS 32768
#define LSEQ   512
#define HID    128
#define VD     256
#define FFND   256
#define QKN    768   // 128 Q | 128 K | 256 V | 256 G

typedef unsigned short u16;

// fp32 row-major buffers
__device__ float g_X [TOKENS * HID];
__device__ float g_Y1[TOKENS * HID];
// bf16 buffers
__device__ u16 g_G [TOKENS * VD];
__device__ u16 g_Xn[TOKENS * HID];
__device__ u16 g_P [TOKENS * VD];
__device__ u16 g_Hf[TOKENS * FFND];
__device__ u16 g_Qf[64*4*16384];
__device__ u16 g_Kf[64*4*16384];
__device__ u16 g_Vf[(size_t)64*4*32768];
__device__ u16 g_Wq[4 * HID * QKN];
__device__ u16 g_Wo[4 * VD * HID];
__device__ u16 g_W1[4 * HID * FFND];
__device__ u16 g_W2[4 * FFND * HID];
__device__ float g_qc[LSEQ*16], g_qs[LSEQ*16], g_kc[LSEQ*16], g_ks[LSEQ*16];
__device__ float g_lg2g[4];

__device__ __forceinline__ float geluf(float v){ return 0.5f*v*(1.0f+erff(v*0.70710678f)); }
__device__ __forceinline__ float siluf(float v){ return v/(1.0f+expf(-v)); }
__device__ __forceinline__ unsigned bf2(float a, float b){
    __nv_bfloat162 t = __floats2bfloat162_rn(a, b);
    return *(unsigned*)&t;
}
__device__ __forceinline__ u16 bf1(float a){
    __nv_bfloat16 t = __float2bfloat16_rn(a);
    return *(u16*)&t;
}
__device__ __forceinline__ float2 unbf2(unsigned u){
    __nv_bfloat162 t = *(__nv_bfloat162*)&u;
    return __bfloat1622float2(t);
}
__device__ __forceinline__ void mma_bf16(float* d, const unsigned* a, const unsigned* b){
    asm volatile("mma.sync.aligned.m16n8k16.row.col.f32.bf16.bf16.f32 "
        "{%0,%1,%2,%3},{%4,%5,%6,%7},{%8,%9},{%0,%1,%2,%3};"
        : "+f"(d[0]),"+f"(d[1]),"+f"(d[2]),"+f"(d[3])
        : "r"(a[0]),"r"(a[1]),"r"(a[2]),"r"(a[3]), "r"(b[0]),"r"(b[1]));
}
__device__ __forceinline__ void cpa16(u16* dst, const u16* src){
    unsigned d = (unsigned)__cvta_generic_to_shared(dst);
    asm volatile("cp.async.cg.shared.global [%0], [%1], 16;" :: "r"(d), "l"(src));
}

// A-fragment ushort index, m16n8k16 bf16. Kt = K/16.
__device__ __forceinline__ size_t a16(int row, int k, int Kt){
    return ((size_t)((row>>4)*Kt + (k>>4)))*256 +
           (size_t)(((row&7)*4 + ((k&7)>>1))*8 + (((row>>3)&1) + (((k>>3)&1)<<1))*2 + (k&1));
}
// B-fragment ushort index
__device__ __forceinline__ size_t b16(int k, int n, int Kt){
    return ((size_t)((n>>3)*Kt + (k>>4)))*128 +
           (size_t)(((n&7)*4 + ((k&7)>>1))*4 + (((k>>3)&1)<<1) + (k&1));
}

// ------------------- xpos tables + per-head log2(gamma) -------------------
__global__ void xpos_table_kernel(){
    int idx = blockIdx.x*256 + threadIdx.x;
    if (idx < 4){
        double lgA=-3.4657359027997265, lgB=-6.2383246250395075;
        g_lg2g[idx] = (float)(log(1.0 - exp(lgA + (lgB-lgA)*(double)idx/3.0)) * 1.4426950408889634);
    }
    if (idx >= LSEQ*16) return;
    int l = idx >> 4, j = idx & 15;
    float base = ((float)j + 12.8f) / 44.8f;
    float sc   = powf(base, (float)l / 512.0f);
    float ang  = (float)l * powf(10000.0f, -(float)j/16.0f);
    float s, c; sincosf(ang, &s, &c);
    g_qc[idx]=c*sc; g_qs[idx]=s*sc; g_kc[idx]=c/sc; g_ks[idx]=s/sc;
}

// ------------------- ALL weights -> bf16 B-fragment layout -------------------
__global__ void wfrag_all_kernel(
    const float* __restrict__ wq, const float* __restrict__ wk,
    const float* __restrict__ wv, const float* __restrict__ wg,
    const float* __restrict__ wo, const float* __restrict__ w1,
    const float* __restrict__ w2)
{
    int idx = blockIdx.x*256 + threadIdx.x;
    int l = idx / 196608, r = idx % 196608;
    if (r < 98304){
        int k = r / QKN, n = r % QKN;
        float v;
        if (n < 128)      v = wq[(((size_t)l*4 + (n>>5))*HID + k)*32 + (n&31)];
        else if (n < 256) { int c=n-128; v = wk[(((size_t)l*4 + (c>>5))*HID + k)*32 + (c&31)]; }
        else if (n < 512) { int c=n-256; v = wv[(((size_t)l*4 + (c>>6))*HID + k)*64 + (c&63)]; }
        else              v = wg[((size_t)l*HID + k)*VD + (n-512)];
        g_Wq[(size_t)l*HID*QKN + b16(k, n, 8)] = bf1(v);
    } else {
        int r2 = r - 98304;
        int m = r2 >> 15, e = r2 & 32767;
        if (m == 0){
            int k = e >> 7, n = e & 127;
            g_Wo[(size_t)l*VD*HID + b16(k, n, 16)] =
                bf1(wo[(size_t)l*VD*HID + (size_t)k*HID + n]);
        } else if (m == 1){
            int k = e >> 8, n = e & 255;
            g_W1[(size_t)l*HID*FFND + b16(k, n, 8)] =
                bf1(w1[(size_t)l*HID*FFND + (size_t)k*FFND + n]);
        } else {
            int k = e >> 7, n = e & 127;
            g_W2[(size_t)l*FFND*HID + b16(k, n, 16)] =
                bf1(w2[(size_t)l*FFND*HID + (size_t)k*HID + n]);
        }
    }
}

// ------------------- input MLP -------------------
__global__ __launch_bounds__(256) void rem_kernel(
    const float* __restrict__ x,
    const float* __restrict__ w1, const float* __restrict__ b1,
    const float* __restrict__ w2, const float* __restrict__ b2,
    const float* __restrict__ w3, const float* __restrict__ b3,
    float* __restrict__ X)
{
    __shared__ float sw1[160], sb1[32], sw2[2048], sb2[64], sw3[8192], sb3[128];
    int tid = threadIdx.x;
    for (int i=tid;i<160; i+=256) sw1[i]=w1[i];
    for (int i=tid;i<2048;i+=256) sw2[i]=w2[i];
    for (int i=tid;i<8192;i+=256) sw3[i]=w3[i];
    if (tid<32)  sb1[tid]=b1[tid];
    if (tid<64)  sb2[tid]=b2[tid];
    if (tid<128) sb3[tid]=b3[tid];
    __syncthreads();
    int t = blockIdx.x*256 + tid;
    float xin[5];
#pragma unroll
    for (int k=0;k<5;k++) xin[k] = x[(size_t)t*5+k];
    float h1[32];
#pragma unroll
    for (int o=0;o<32;o++){ float s=sb1[o];
#pragma unroll
        for (int k=0;k<5;k++) s += xin[k]*sw1[k*32+o];
        h1[o]=geluf(s); }
    float h2[64];
#pragma unroll
    for (int o=0;o<64;o++){ float s=sb2[o];
#pragma unroll
        for (int k=0;k<32;k++) s += h1[k]*sw2[k*64+o];
        h2[o]=geluf(s); }
    for (int o=0;o<128;o+=4){
        float v0=sb3[o],v1=sb3[o+1],v2=sb3[o+2],v3=sb3[o+3];
#pragma unroll
        for (int k=0;k<64;k++){ float hk=h2[k];
            v0+=hk*sw3[k*128+o]; v1+=hk*sw3[k*128+o+1];
            v2+=hk*sw3[k*128+o+2]; v3+=hk*sw3[k*128+o+3]; }
        *(float4*)(X+(size_t)t*128+o) = make_float4(geluf(v0),geluf(v1),geluf(v2),geluf(v3));
    }
}

// ------------------- LayerNorm(128) -> bf16 A-fragment layout -------------------
__global__ __launch_bounds__(256) void ln_frag_kernel(
    const float* __restrict__ X, const float* __restrict__ w,
    const float* __restrict__ b, u16* __restrict__ out)
{
    int g = blockIdx.x*256 + threadIdx.x;
    int row = g>>5, lane = g&31;
    float4 v = *(const float4*)(X + (size_t)row*128 + lane*4);
    float s = v.x+v.y+v.z+v.w;
    float s2 = v.x*v.x+v.y*v.y+v.z*v.z+v.w*v.w;
#pragma unroll
    for (int o=16;o;o>>=1){ s += __shfl_xor_sync(~0u,s,o); s2 += __shfl_xor_sync(~0u,s2,o); }
    float mean = s*(1.f/128.f), var = s2*(1.f/128.f)-mean*mean;
    float rstd = rsqrtf(var + 1e-5f);
    float4 wv = *(const float4*)(w+lane*4), bv = *(const float4*)(b+lane*4);
    float rv[4];
    rv[0]=(v.x-mean)*rstd*wv.x+bv.x; rv[1]=(v.y-mean)*rstd*wv.y+bv.y;
    rv[2]=(v.z-mean)*rstd*wv.z+bv.z; rv[3]=(v.w-mean)*rstd*wv.w+bv.w;
    int k0 = lane*4;
    *(unsigned*)(out + a16(row, k0,   8)) = bf2(rv[0], rv[1]);
    *(unsigned*)(out + a16(row, k0+2, 8)) = bf2(rv[2], rv[3]);
}

// ------------------- bf16 frag-fed GEMM, 256x64 block. OP: 1 gelu->Afrag, 3 residual ----
template<int OP>
__global__ __launch_bounds__(256) void gemm_f(
    const u16* __restrict__ Af, const u16* __restrict__ Bf,
    const float* __restrict__ bias, const float* __restrict__ R,
    float* __restrict__ Cf, u16* __restrict__ Ca, int N, int K)
{
    const int tid = threadIdx.x, lane = tid & 31, wid = tid >> 5;
    const int wm = wid & 3, wn = wid >> 2;
    const int m0 = blockIdx.y*256, n0 = blockIdx.x*64;
    const int Kt = K >> 4;

    float acc[4][4][4];
#pragma unroll
    for (int i=0;i<4;i++)
#pragma unroll
        for (int j=0;j<4;j++)
#pragma unroll
            for (int u=0;u<4;u++) acc[i][j][u]=0.f;

    const u16* Ab = Af + ((size_t)((m0>>4) + wm*4))*Kt*256 + lane*8;
    const u16* Bb = Bf + ((size_t)((n0>>3) + wn*4))*Kt*128 + lane*4;

#pragma unroll 2
    for (int kc = 0; kc < Kt; kc++){
        unsigned a[4][4], b[4][2];
#pragma unroll
        for (int mi=0;mi<4;mi++){
            uint4 t = *(const uint4*)(Ab + ((size_t)(mi*Kt + kc))*256);
            a[mi][0]=t.x; a[mi][1]=t.y; a[mi][2]=t.z; a[mi][3]=t.w;
        }
#pragma unroll
        for (int ni=0;ni<4;ni++){
            uint2 t = *(const uint2*)(Bb + ((size_t)(ni*Kt + kc))*128);
            b[ni][0]=t.x; b[ni][1]=t.y;
        }
#pragma unroll
        for (int mi=0;mi<4;mi++)
#pragma unroll
            for (int ni=0;ni<4;ni++)
                mma_bf16(acc[mi][ni], a[mi], b[ni]);
    }

    const int gid = lane>>2, tig = lane&3;
#pragma unroll
    for (int mi=0;mi<4;mi++)
#pragma unroll
        for (int ni=0;ni<4;ni++){
            int col = n0 + wn*32 + ni*8 + tig*2;
            float bb0=0.f, bb1=0.f;
            if (bias){ float2 bv = *(const float2*)(bias+col); bb0=bv.x; bb1=bv.y; }
#pragma unroll
            for (int hh=0; hh<2; hh++){
                int row = m0 + wm*64 + mi*16 + gid + hh*8;
                float v0 = acc[mi][ni][hh*2+0] + bb0;
                float v1 = acc[mi][ni][hh*2+1] + bb1;
                if (OP==1){
                    v0 = geluf(v0); v1 = geluf(v1);
                    *(unsigned*)(Ca + a16(row, col, N>>4)) = bf2(v0, v1);
                } else {
                    float2 rv = *(const float2*)(R + (size_t)row*N + col);
                    v0+=rv.x; v1+=rv.y;
                    *(float2*)(Cf + (size_t)row*N + col) = make_float2(v0,v1);
                }
            }
        }
}

// ------------------- QKVG GEMM: 256x64 block, epilogue -> per-head bf16 frag buffers ----
__global__ __launch_bounds__(256) void gemm_qkvg(
    const u16* __restrict__ Af, const u16* __restrict__ Bf)
{
    const int tid = threadIdx.x, lane = tid & 31, wid = tid >> 5;
    const int wm = wid & 3, wn = wid >> 2;
    const int m0 = blockIdx.y*256, n0 = blockIdx.x*64;
    const int Kt = 8;

    float acc[4][4][4];
#pragma unroll
    for (int i=0;i<4;i++)
#pragma unroll
        for (int j=0;j<4;j++)
#pragma unroll
            for (int u=0;u<4;u++) acc[i][j][u]=0.f;

    const u16* Ab = Af + ((size_t)((m0>>4) + wm*4))*Kt*256 + lane*8;
    const u16* Bb = Bf + ((size_t)((n0>>3) + wn*4))*Kt*128 + lane*4;

#pragma unroll 2
    for (int kc = 0; kc < Kt; kc++){
        unsigned a[4][4], b[4][2];
#pragma unroll
        for (int mi=0;mi<4;mi++){
            uint4 t = *(const uint4*)(Ab + ((size_t)(mi*Kt + kc))*256);
            a[mi][0]=t.x; a[mi][1]=t.y; a[mi][2]=t.z; a[mi][3]=t.w;
        }
#pragma unroll
        for (int ni=0;ni<4;ni++){
            uint2 t = *(const uint2*)(Bb + ((size_t)(ni*Kt + kc))*128);
            b[ni][0]=t.x; b[ni][1]=t.y;
        }
#pragma unroll
        for (int mi=0;mi<4;mi++)
#pragma unroll
            for (int ni=0;ni<4;ni++)
                mma_bf16(acc[mi][ni], a[mi], b[ni]);
    }

    const int gid = lane>>2, tig = lane&3;
#pragma unroll
    for (int mi=0;mi<4;mi++)
#pragma unroll
        for (int ni=0;ni<4;ni++){
            int col = n0 + wn*32 + ni*8 + tig*2;
#pragma unroll
            for (int hh=0; hh<2; hh++){
                int t = m0 + wm*64 + mi*16 + gid + hh*8;
                int bb = t >> 9, ii = t & 511;
                float v0 = acc[mi][ni][hh*2+0];
                float v1 = acc[mi][ni][hh*2+1];
                if (col < 256){
                    const float* ct = (col<128)? g_qc : g_kc;
                    const float* st = (col<128)? g_qs : g_ks;
                    int j = (col&31)>>1;
                    float c0=ct[ii*16+j], s0=st[ii*16+j];
                    float t0 = v0*c0 - v1*s0, t1 = v1*c0 + v0*s0;
                    if (col < 128){
                        int h = col>>5, d = col&31;
                        float sc = exp2f((float)ii * g_lg2g[h]);
                        u16* dst = g_Qf + ((size_t)(bb*4+h))*16384;
                        *(unsigned*)(dst + a16(ii, d, 2)) = bf2(t0*sc, t1*sc);
                    } else {
                        int h = (col-128)>>5, d = (col-128)&31;
                        float sc = exp2f(-(float)ii * g_lg2g[h]);
                        u16* dst = g_Kf + ((size_t)(bb*4+h))*16384;
                        *(unsigned*)(dst + b16(d, ii, 2)) = bf2(t0*sc, t1*sc);
                    }
                } else if (col < 512){
                    int h = (col-256)>>6, v = (col-256)&63;
                    u16* dst = g_Vf + ((size_t)(bb*4+h))*32768;
                    dst[b16(ii, v,   32)] = bf1(v0);
                    dst[b16(ii, v+1, 32)] = bf1(v1);
                } else {
                    *(unsigned*)(g_G + (size_t)t*VD + (col-512)) = bf2(v0, v1);
                }
            }
        }
}

// ------------------- Retention: S in registers, cp.async double-buffered K/V -------------------
// heavy-first scheduling: qt = 3 - blockIdx.x (LPT)
#define RET_SMEM 24576
__global__ __launch_bounds__(256) void retention_kernel(
    const u16* __restrict__ Qf, const u16* __restrict__ Kf,
    const u16* __restrict__ Vf, const u16* __restrict__ G,
    const float* __restrict__ gn_w, const float* __restrict__ gn_b,
    u16* __restrict__ P)
{
    extern __shared__ u16 smu[];
    u16* KsB = smu;          // 2 x 2048
    u16* VsB = smu + 4096;   // 2 x 4096

    const int tid = threadIdx.x, lane = tid&31, wm = tid>>5;
    const int gid = lane>>2, tig = lane&3;
    const int qt = (int)(gridDim.x - 1) - (int)blockIdx.x;   // heavy blocks first
    const int h = blockIdx.y, b = blockIdx.z;
    const int l0 = qt*128;
    const size_t rb = (size_t)b*512;
    const size_t bh = (size_t)(b*4 + h);
    const u16* Qg = Qf + bh*16384;
    const u16* Kg = Kf + bh*16384;
    const u16* Vg = Vf + bh*32768;

    unsigned qf[2][4];
#pragma unroll
    for (int kc=0; kc<2; kc++){
        uint4 t = *(const uint4*)(Qg + ((size_t)(((l0>>4)+wm)*2 + kc))*256 + lane*8);
        qf[kc][0]=t.x; qf[kc][1]=t.y; qf[kc][2]=t.z; qf[kc][3]=t.w;
    }

    float yacc[8][4];
#pragma unroll
    for (int j=0;j<8;j++)
#pragma unroll
        for (int u=0;u<4;u++) yacc[j][u]=0.f;

    const int ntile = 2*qt + 2;
    const int vg0 = tid >> 6, vrem0 = tid & 63;
    const int vg1 = (tid+256) >> 6, vrem1 = (tid+256) & 63;

    {
        cpa16(KsB + tid*8, Kg + (size_t)0*2048 + tid*8);
        cpa16(VsB + (size_t)tid*8,        Vg + ((size_t)(vg0*32 + 0*4)*16 + vrem0)*8);
        cpa16(VsB + (size_t)(tid+256)*8,  Vg + ((size_t)(vg1*32 + 0*4)*16 + vrem1)*8);
        asm volatile("cp.async.commit_group;");
    }

    for (int mt=0; mt<ntile; mt++){
        const int cur = mt & 1;
        const int doff = mt*64 - l0;
        if (mt+1 < ntile){
            int nb = cur ^ 1;
            cpa16(KsB + nb*2048 + tid*8, Kg + (size_t)(mt+1)*2048 + tid*8);
            cpa16(VsB + nb*4096 + (size_t)tid*8,       Vg + ((size_t)(vg0*32 + (mt+1)*4)*16 + vrem0)*8);
            cpa16(VsB + nb*4096 + (size_t)(tid+256)*8, Vg + ((size_t)(vg1*32 + (mt+1)*4)*16 + vrem1)*8);
            asm volatile("cp.async.commit_group;");
            asm volatile("cp.async.wait_group 1;");
        } else {
            asm volatile("cp.async.wait_group 0;");
        }
        __syncthreads();

        const u16* Ks = KsB + cur*2048;
        const u16* Vs = VsB + cur*4096;

        float sacc[8][4];
#pragma unroll
        for (int j=0;j<8;j++)
#pragma unroll
            for (int u=0;u<4;u++) sacc[j][u]=0.f;
#pragma unroll
        for (int kc=0; kc<2; kc++){
#pragma unroll
            for (int nj=0;nj<8;nj++){
                uint2 bt = *(const uint2*)(Ks + (size_t)(nj*2+kc)*128 + lane*4);
                unsigned bfr[2] = {bt.x, bt.y};
                mma_bf16(sacc[nj], qf[kc], bfr);
            }
        }
        if (doff >= 0){
#pragma unroll
            for (int nj=0;nj<8;nj++){
                int jb = nj*8 + tig*2 + doff;
#pragma unroll
                for (int ih=0; ih<2; ih++){
                    int i = wm*16 + gid + ih*8;
                    if (i < jb)   sacc[nj][ih*2+0] = 0.f;
                    if (i < jb+1) sacc[nj][ih*2+1] = 0.f;
                }
            }
        }
#pragma unroll
        for (int kc=0; kc<4; kc++){
            unsigned a[4];
            a[0] = bf2(sacc[2*kc  ][0], sacc[2*kc  ][1]);
            a[1] = bf2(sacc[2*kc  ][2], sacc[2*kc  ][3]);
            a[2] = bf2(sacc[2*kc+1][0], sacc[2*kc+1][1]);
            a[3] = bf2(sacc[2*kc+1][2], sacc[2*kc+1][3]);
#pragma unroll
            for (int nj=0;nj<8;nj++){
                uint2 bt = *(const uint2*)(Vs + (size_t)(nj*4+kc)*128 + lane*4);
                unsigned bfr[2] = {bt.x, bt.y};
                mma_bf16(yacc[nj], a, bfr);
            }
        }
        __syncthreads();
    }

    float s[2]={0.f,0.f}, q[2]={0.f,0.f};
#pragma unroll
    for (int nj=0;nj<8;nj++){
#pragma unroll
        for (int ih=0; ih<2; ih++){
            float v0 = yacc[nj][ih*2+0], v1 = yacc[nj][ih*2+1];
            s[ih] += v0 + v1;
            q[ih] += v0*v0 + v1*v1;
        }
    }
#pragma unroll
    for (int o=1;o<4;o<<=1){
        s[0] += __shfl_xor_sync(~0u, s[0], o);
        q[0] += __shfl_xor_sync(~0u, q[0], o);
        s[1] += __shfl_xor_sync(~0u, s[1], o);
        q[1] += __shfl_xor_sync(~0u, q[1], o);
    }
    float mean[2], rstd[2];
#pragma unroll
    for (int ih=0; ih<2; ih++){
        mean[ih] = s[ih]*(1.f/64.f);
        float var = q[ih]*(1.f/64.f) - mean[ih]*mean[ih];
        rstd[ih] = rsqrtf(var + 1e-5f);
    }
#pragma unroll
    for (int nj=0;nj<8;nj++){
        int col = nj*8 + tig*2;
        int k = h*64 + col;
        float2 wv = *(const float2*)(gn_w + k);
        float2 bv = *(const float2*)(gn_b + k);
#pragma unroll
        for (int ih=0; ih<2; ih++){
            int rowt = (int)(rb + l0 + wm*16 + gid + ih*8);
            unsigned gp = *(const unsigned*)(G + (size_t)rowt*VD + k);
            float2 gg = unbf2(gp);
            float o0 = ((yacc[nj][ih*2+0]-mean[ih])*rstd[ih]*wv.x + bv.x)*siluf(gg.x);
            float o1 = ((yacc[nj][ih*2+1]-mean[ih])*rstd[ih]*wv.y + bv.y)*siluf(gg.y);
            *(unsigned*)(P + a16(rowt, k, 16)) = bf2(o0, o1);
        }
    }
}

// ------------------- decoder + softmax -------------------
__global__ __launch_bounds__(256) void dec_kernel(
    const float* __restrict__ X, const float* __restrict__ w1, const float* __restrict__ b1,
    const float* __restrict__ w2, const float* __restrict__ b2, float* __restrict__ out)
{
    __shared__ float sw1[8192], sw2[1280], sb1[64], sb2[20];
    int tid = threadIdx.x;
    for (int i=tid;i<8192;i+=256) sw1[i]=w1[i];
    for (int i=tid;i<1280;i+=256) sw2[i]=w2[i];
    if (tid<64) sb1[tid]=b1[tid];
    if (tid<20) sb2[tid]=b2[tid];
    __syncthreads();
    int t = blockIdx.x*256 + tid;
    float h[64];
#pragma unroll
    for (int o=0;o<64;o++) h[o]=sb1[o];
    for (int k=0;k<128;k+=4){
        float4 xv = *(const float4*)(X + (size_t)t*128 + k);
#pragma unroll
        for (int o=0;o<64;o++){
            h[o] += xv.x*sw1[(k+0)*64+o] + xv.y*sw1[(k+1)*64+o]
                  + xv.z*sw1[(k+2)*64+o] + xv.w*sw1[(k+3)*64+o];
        }
    }
#pragma unroll
    for (int o=0;o<64;o++) h[o]=geluf(h[o]);
    float lg[20];
#pragma unroll
    for (int o=0;o<20;o++){ float s=sb2[o];
#pragma unroll
        for (int k=0;k<64;k++) s += h[k]*sw2[k*20+o];
        lg[o]=s; }
    float mx = lg[0];
#pragma unroll
    for (int o=1;o<20;o++) mx = fmaxf(mx, lg[o]);
    float sum = 0.f;
#pragma unroll
    for (int o=0;o<20;o++){ lg[o] = expf(lg[o]-mx); sum += lg[o]; }
    float inv = 1.0f/sum;
#pragma unroll
    for (int o=0;o<20;o++) out[(size_t)t*20+o] = lg[o]*inv;
}

// ------------------- launch -------------------
extern "C" void kernel_launch(void* const* d_in, const int* in_sizes, int n_in,
                              void* d_out, int out_size)
{
    const float* x      = (const float*)d_in[0];
    const float* rem_w1 = (const float*)d_in[1];
    const float* rem_b1 = (const float*)d_in[2];
    const float* rem_w2 = (const float*)d_in[3];
    const float* rem_b2 = (const float*)d_in[4];
    const float* rem_w3 = (const float*)d_in[5];
    const float* rem_b3 = (const float*)d_in[6];
    const float* wq     = (const float*)d_in[7];
    const float* wk     = (const float*)d_in[8];
    const float* wv     = (const float*)d_in[9];
    const float* wg     = (const float*)d_in[10];
    const float* wo     = (const float*)d_in[11];
    const float* gn_w   = (const float*)d_in[12];
    const float* gn_b   = (const float*)d_in[13];
    const float* ln1_w  = (const float*)d_in[14];
    const float* ln1_b  = (const float*)d_in[15];
    const float* ln2_w  = (const float*)d_in[16];
    const float* ln2_b  = (const float*)d_in[17];
    const float* ffn_w1 = (const float*)d_in[18];
    const float* ffn_b1 = (const float*)d_in[19];
    const float* ffn_w2 = (const float*)d_in[20];
    const float* ffn_b2 = (const float*)d_in[21];
    const float* dec_w1 = (const float*)d_in[22];
    const float* dec_b1 = (const float*)d_in[23];
    const float* dec_w2 = (const float*)d_in[24];
    const float* dec_b2 = (const float*)d_in[25];
    float* out = (float*)d_out;

    float *pX,*pY1;
    u16 *pG,*pXn,*pP,*pHf,*pWq,*pWo,*pW1,*pW2,*pQf,*pKf,*pVf;
    cudaGetSymbolAddress((void**)&pX,  g_X);
    cudaGetSymbolAddress((void**)&pY1, g_Y1);
    cudaGetSymbolAddress((void**)&pG,  g_G);
    cudaGetSymbolAddress((void**)&pXn, g_Xn);
    cudaGetSymbolAddress((void**)&pP,  g_P);
    cudaGetSymbolAddress((void**)&pHf, g_Hf);
    cudaGetSymbolAddress((void**)&pWq, g_Wq);
    cudaGetSymbolAddress((void**)&pWo, g_Wo);
    cudaGetSymbolAddress((void**)&pW1, g_W1);
    cudaGetSymbolAddress((void**)&pW2, g_W2);
    cudaGetSymbolAddress((void**)&pQf, g_Qf);
    cudaGetSymbolAddress((void**)&pKf, g_Kf);
    cudaGetSymbolAddress((void**)&pVf, g_Vf);

    xpos_table_kernel<<<32, 256>>>();
    wfrag_all_kernel<<<(4*196608)/256, 256>>>(wq, wk, wv, wg, wo, ffn_w1, ffn_w2);
    rem_kernel<<<TOKENS/256, 256>>>(x, rem_w1, rem_b1, rem_w2, rem_b2, rem_w3, rem_b3, pX);

    for (int l = 0; l < 4; l++){
        ln_frag_kernel<<<TOKENS/8, 256>>>(pX, ln1_w + l*128, ln1_b + l*128, pXn);
        gemm_qkvg<<<dim3(QKN/64, TOKENS/256), 256>>>(pXn, pWq + (size_t)l*HID*QKN);
        retention_kernel<<<dim3(4, 4, 64), 256, RET_SMEM>>>(
            pQf, pKf, pVf, pG, gn_w + l*VD, gn_b + l*VD, pP);
        gemm_f<3><<<dim3(HID/64, TOKENS/256), 256>>>(
            pP, pWo + (size_t)l*VD*HID, nullptr, pX, pY1, nullptr, HID, VD);
        ln_frag_kernel<<<TOKENS/8, 256>>>(pY1, ln2_w + l*128, ln2_b + l*128, pXn);
        gemm_f<1><<<dim3(FFND/64, TOKENS/256), 256>>>(
            pXn, pW1 + (size_t)l*HID*FFND, ffn_b1 + l*FFND, nullptr, nullptr, pHf, FFND, HID);
        gemm_f<3><<<dim3(HID/64, TOKENS/256), 256>>>(
            pHf, pW2 + (size_t)l*FFND*HID, ffn_b2 + l*HID, pY1, pX, nullptr, HID, FFND);
    }
    dec_kernel<<<TOKENS/256, 256>>>(pX, dec_w1, dec_b1, dec_w2, dec_b2, out);
}